// round 11
// baseline (speedup 1.0000x reference)
#include <cuda_runtime.h>

#define G       180
#define NA      64
#define Bx      27
#define RMAX    13
#define SPLIT   2
#define THREADS 384
#define NWARP   (THREADS/32)     // 12
#define AH      0.2f
#define ROF     2.5f
#define RO2F    6.25f
#define VCELLF  0.008f
#define NCOL    (Bx*Bx)          // 729
#define RSTR    36               // staged row stride (floats): 144B, 16B-aligned
#define DSMEM   (THREADS*RSTR*4) // 55296 bytes

__device__ float        g_partial[NA * SPLIT * 128];
__device__ unsigned int g_count[NA];

typedef unsigned long long u64;

__device__ __forceinline__ u64 pk2(float lo, float hi) {
    u64 r; asm("mov.b64 %0, {%1, %2};" : "=l"(r) : "f"(lo), "f"(hi)); return r;
}
__device__ __forceinline__ u64 pk1(float v) {     // (v, v)
    u64 r; asm("mov.b64 %0, {%1, %1};" : "=l"(r) : "f"(v)); return r;
}
__device__ __forceinline__ void fma2(u64& d, u64 a, u64 b) {
    asm("fma.rn.f32x2 %0, %1, %2, %0;" : "+l"(d) : "l"(a), "l"(b));
}
__device__ __forceinline__ u64 mul2(u64 a, u64 b) {
    u64 r; asm("mul.rn.f32x2 %0, %1, %2;" : "=l"(r) : "l"(a), "l"(b)); return r;
}
__device__ __forceinline__ void add2(u64& d, u64 a) {
    asm("add.rn.f32x2 %0, %0, %1;" : "+l"(d) : "l"(a));
}

extern __shared__ float dynbuf[];   // THREADS x RSTR floats

__global__ __launch_bounds__(THREADS)
void proj_kernel(const float* __restrict__ rho, const float* __restrict__ pos,
                 const float* __restrict__ W, float* __restrict__ out)
{
    const int blk  = blockIdx.x;
    const int atom = blk >> 1;          // SPLIT = 2 (column parity)
    const int part = blk & 1;
    const int tid  = threadIdx.x;

    __shared__ float2 ztab[32];          // { z, zindex(asfloat) }, padded
    __shared__ float  sseg[12 * 32];
    __shared__ float  scomb[128];
    __shared__ unsigned int slast;

    const float px = pos[atom*3+0];
    const float py = pos[atom*3+1];
    const float pz = pos[atom*3+2];
    const float cmx = rintf(px * 5.0f);
    const float cmy = rintf(py * 5.0f);
    const float cmz = rintf(pz * 5.0f);
    const int cx = (int)cmx, cy = (int)cmy, cz = (int)cmz;
    const float dx = px - AH * cmx;
    const float dy = py - AH * cmy;
    const float dz = pz - AH * cmz;

    if (tid < 32) {
        const int kk = min(tid, Bx - 1);          // pad 27..31 with k=26
        int vz = cz + (kk - RMAX);
        vz += (vz < 0) ? G : 0;  vz -= (vz >= G) ? G : 0;
        const float zs = (float)(kk - RMAX) * AH - dz;
        ztab[tid] = make_float2(zs, __int_as_float(vz));
    }
    __syncthreads();

    // ---- ring-ordered column assignment: 1 column per thread ----
    const int cidx   = 2 * tid + part;
    const bool activ = (cidx < NCOL);
    const int cc     = activ ? cidx : 0;

    int i, j;
    {
        const float rf = sqrtf((float)cc);
        const int rr = (int)((rf + 1.0f) * 0.5f);
        if (rr == 0) { i = RMAX; j = RMAX; }
        else {
            const int t    = cc - (2*rr - 1) * (2*rr - 1);
            const int side = t / (2*rr);
            const int posn = t - side * (2*rr);
            if      (side == 0) { i = RMAX - rr;        j = RMAX - rr + posn; }
            else if (side == 1) { i = RMAX - rr + posn; j = RMAX + rr; }
            else if (side == 2) { i = RMAX + rr;        j = RMAX + rr - posn; }
            else                { i = RMAX + rr - posn; j = RMAX - rr; }
        }
    }

    const int di = i - RMAX, dj = j - RMAX;
    int vx = cx + di;  vx += (vx < 0) ? G : 0;  vx -= (vx >= G) ? G : 0;
    int vy = cy + dj;  vy += (vy < 0) ? G : 0;  vy -= (vy >= G) ? G : 0;
    const int rowbase = (vx * G + vy) * G;
    const float x   = (float)di * AH - dx;
    const float y   = (float)dj * AH - dy;
    const float c2d = x * x + y * y;
    const float s2  = RO2F - c2d;

    int kmin = 1, kmax = 0;
    if (activ && s2 > 0.0f) {
        const float sq = sqrtf(s2);
        kmin = max(0,  (int)floorf(13.0f + (dz - sq) * 5.0f));
        kmax = min(26, (int)ceilf (13.0f + (dz + sq) * 5.0f));
    }

    // ---- moment accumulators: M[l][d], packed over m-pairs k=0..3 ----
    u64 M00[4], M10[4], M11[4], M20[4], M21[4], M22[4];
    u64 M30[4], M31[4], M32[4], M33[4];
    #pragma unroll
    for (int k = 0; k < 4; k++) {
        M00[k]=0; M10[k]=0; M11[k]=0; M20[k]=0; M21[k]=0; M22[k]=0;
        M30[k]=0; M31[k]=0; M32[k]=0; M33[k]=0;
    }

    if (kmin <= kmax) {
        float2 zz0 = ztab[kmin];
        float2 zz1 = ztab[kmin + 1];
        float  sr0 = __ldg(rho + rowbase + __float_as_int(zz0.y));
        float  sr1 = __ldg(rho + rowbase + __float_as_int(zz1.y));

        #pragma unroll 1
        for (int k = kmin; k <= kmax; k += 2) {
            float2 nz0 = ztab[k + 2];
            float2 nz1 = ztab[k + 3];
            float  nr0 = __ldg(rho + rowbase + __float_as_int(nz0.y));
            float  nr1 = __ldg(rho + rowbase + __float_as_int(nz1.y));

            const float msk = (k + 1 <= kmax) ? 1.0f : 0.0f;
            #pragma unroll
            for (int s = 0; s < 2; s++) {
                const float z    = s ? zz1.x : zz0.x;
                const float srho = s ? sr1 * msk : sr0;

                const float r2  = fmaf(z, z, c2d);
                const float inv = rsqrtf(fmaxf(r2, 1e-24f));
                const float r   = r2 * inv;
                const float u   = fmaxf(ROF - r, 0.0f);
                const float p0  = r2 * u * u * srho;
                const float u2  = u * u;
                const float z2  = z * z;

                const u64 UU = pk1(u2);
                const u64 IV = pk1(inv);
                const u64 Z1 = pk1(z);
                const u64 Z2 = pk1(z2);
                const u64 Z3 = pk1(z2 * z);

                u64 w0 = pk2(p0, p0 * u);     // (p0 u^{2k}, p0 u^{2k+1})
                #pragma unroll
                for (int q = 0; q < 4; q++) {
                    const u64 wl1 = mul2(w0,  IV);
                    const u64 wl2 = mul2(wl1, IV);
                    const u64 wl3 = mul2(wl2, IV);
                    add2(M00[q], w0);
                    add2(M10[q], wl1);  fma2(M11[q], wl1, Z1);
                    add2(M20[q], wl2);  fma2(M21[q], wl2, Z1);  fma2(M22[q], wl2, Z2);
                    add2(M30[q], wl3);  fma2(M31[q], wl3, Z1);  fma2(M32[q], wl3, Z2);
                    fma2(M33[q], wl3, Z3);
                    if (q < 3) w0 = mul2(w0, UU);
                }
            }
            zz0 = nz0;  zz1 = nz1;  sr0 = nr0;  sr1 = nr1;
        }
    }

    // ---- per-column transform constants (packed) ----
    const float xy  = x * y;
    const float x2  = x * x, y2 = y * y;
    const float sp  = x2 + y2, sm = x2 - y2;
    const u64 K0  = pk1(0.28209479177387814f);
    const u64 A1  = pk1(0.4886025119029199f * y);
    const u64 K2  = pk1(0.4886025119029199f);
    const u64 A3  = pk1(0.4886025119029199f * x);
    const u64 A4  = pk1(1.0925484305920792f * xy);
    const u64 A5  = pk1(1.0925484305920792f * y);
    const u64 K6  = pk1(0.6307831305050401f);
    const u64 A6  = pk1(-0.31539156525252005f * sp);
    const u64 A7  = pk1(1.0925484305920792f * x);
    const u64 A8  = pk1(0.5462742152960396f * sm);
    const u64 A9  = pk1(0.5900435899266435f * y * (3.0f * x2 - y2));
    const u64 A10 = pk1(2.890611442640554f * xy);
    const u64 B11 = pk1(1.8281831978578632f * y);
    const u64 A11 = pk1(-0.4570457994644658f * y * sp);
    const u64 K12 = pk1(0.7463526651802308f);
    const u64 A12 = pk1(-1.1195289977703462f * sp);
    const u64 B13 = pk1(1.8281831978578632f * x);
    const u64 A13 = pk1(-0.4570457994644658f * x * sp);
    const u64 A14 = pk1(1.445305721320277f * sm);
    const u64 A15 = pk1(0.5900435899266435f * x * (x2 - 3.0f * y2));

    // ---- 4 staging/reduce passes, one per m-pair ----
    #pragma unroll 1
    for (int kp = 0; kp < 4; kp++) {
        u64 c[16];
        c[0]  = mul2(K0,  M00[kp]);
        c[1]  = mul2(A1,  M10[kp]);
        c[2]  = mul2(K2,  M11[kp]);
        c[3]  = mul2(A3,  M10[kp]);
        c[4]  = mul2(A4,  M20[kp]);
        c[5]  = mul2(A5,  M21[kp]);
        c[6]  = mul2(A6,  M20[kp]);  fma2(c[6],  K6,  M22[kp]);
        c[7]  = mul2(A7,  M21[kp]);
        c[8]  = mul2(A8,  M20[kp]);
        c[9]  = mul2(A9,  M30[kp]);
        c[10] = mul2(A10, M31[kp]);
        c[11] = mul2(A11, M30[kp]);  fma2(c[11], B11, M32[kp]);
        c[12] = mul2(A12, M31[kp]);  fma2(c[12], K12, M33[kp]);
        c[13] = mul2(A13, M30[kp]);  fma2(c[13], B13, M32[kp]);
        c[14] = mul2(A14, M31[kp]);
        c[15] = mul2(A15, M30[kp]);

        // stage: row tid, floats [2q]=c.lo (m=2kp), [2q+1]=c.hi (m=2kp+1)
        {
            float* row = dynbuf + tid * RSTR;
            #pragma unroll
            for (int q = 0; q < 16; q += 2)
                *reinterpret_cast<ulonglong2*>(row + 2 * q) =
                    make_ulonglong2(c[q], c[q + 1]);
        }
        __syncthreads();

        // reduce1: 12 segments x 32 rows -> sseg[seg][v]
        {
            const int v   = tid & 31;
            const int seg = tid >> 5;           // 0..11
            const float* src = dynbuf + (seg * 32) * RSTR + v;
            float a0=0, a1=0, a2=0, a3=0;
            #pragma unroll
            for (int r = 0; r < 32; r += 4) {
                a0 += src[(r+0) * RSTR];
                a1 += src[(r+1) * RSTR];
                a2 += src[(r+2) * RSTR];
                a3 += src[(r+3) * RSTR];
            }
            sseg[seg * 32 + v] = (a0 + a1) + (a2 + a3);
        }
        __syncthreads();

        // reduce2: fold 12 segments -> scomb[m*16+q]
        if (tid < 32) {
            float s = 0.0f;
            #pragma unroll
            for (int g = 0; g < 12; g += 4)
                s += ((sseg[(g+0)*32 + tid] + sseg[(g+1)*32 + tid]) +
                      (sseg[(g+2)*32 + tid] + sseg[(g+3)*32 + tid]));
            const int q  = tid >> 1;
            const int ml = tid & 1;
            scomb[(2 * kp + ml) * 16 + q] = s;
        }
        __syncthreads();
    }

    if (tid < 128) g_partial[blk * 128 + tid] = scomb[tid];
    __threadfence();
    __syncthreads();

    if (tid == 0) {
        const unsigned int ticket = atomicAdd(&g_count[atom], 1u);
        slast = (ticket == SPLIT - 1) ? 1u : 0u;
    }
    __syncthreads();

    if (slast) {
        const volatile float* gp = g_partial;
        if (tid < 128) {
            float s = 0.0f;
            #pragma unroll
            for (int p = 0; p < SPLIT; p++)
                s += gp[(atom * SPLIT + p) * 128 + tid];
            sseg[tid] = s;          // reuse as combine buffer
        }
        __syncthreads();
        if (tid < 128) {
            const int n = tid >> 4;
            const int q = tid & 15;
            float o = 0.0f;
            #pragma unroll
            for (int m = 0; m < 8; m++)
                o = fmaf(W[n * 8 + m], sseg[m * 16 + q], o);
            out[atom * 128 + tid] = o * VCELLF;
        }
        if (tid == 0) g_count[atom] = 0u;
    }
}

extern "C" void kernel_launch(void* const* d_in, const int* in_sizes, int n_in,
                              void* d_out, int out_size)
{
    const float* rho = (const float*)d_in[0];   // 180^3
    const float* pos = (const float*)d_in[1];   // 64 x 3
    const float* W   = (const float*)d_in[2];   // 8 x 8
    float* out = (float*)d_out;                 // 64 x 128

    cudaFuncSetAttribute(proj_kernel,
                         cudaFuncAttributeMaxDynamicSharedMemorySize, DSMEM);
    proj_kernel<<<NA * SPLIT, THREADS, DSMEM>>>(rho, pos, W, out);
}